// round 7
// baseline (speedup 1.0000x reference)
#include <cuda_runtime.h>
#include <cuda_bf16.h>
#include <math.h>
#include <stdint.h>

#define MTOK   4096
#define WIDTH  1024
#define HEADS  16
#define HDIM   64
#define HIDDEN 4096
#define SEQ    2048

__device__ float g_h   [MTOK * WIDTH];
__device__ float g_qkv [MTOK * 3 * WIDTH];
__device__ float g_attn[MTOK * WIDTH];
__device__ float g_x1  [MTOK * WIDTH];
__device__ float g_fc1 [MTOK * HIDDEN];
__device__ float g_wqkv_r [WIDTH * 3 * WIDTH];
__device__ float g_wproj_r[WIDTH * WIDTH];
__device__ float g_wfc1_r [WIDTH * HIDDEN];
__device__ float g_wfc2_r [HIDDEN * WIDTH];

__device__ __forceinline__ float warp_sum(float v) {
    #pragma unroll
    for (int o = 16; o > 0; o >>= 1) v += __shfl_xor_sync(0xffffffffu, v, o);
    return v;
}

__device__ __forceinline__ float tf32r(float x) {
    uint32_t u;
    asm("cvt.rna.tf32.f32 %0, %1;" : "=r"(u) : "f"(x));
    return __uint_as_float(u);
}

__device__ __forceinline__ void mma_tf32(float c[4], const uint32_t a[4], const uint32_t b[2]) {
    asm volatile(
        "mma.sync.aligned.m16n8k8.row.col.f32.tf32.tf32.f32 "
        "{%0,%1,%2,%3}, {%4,%5,%6,%7}, {%8,%9}, {%0,%1,%2,%3};\n"
        : "+f"(c[0]), "+f"(c[1]), "+f"(c[2]), "+f"(c[3])
        : "r"(a[0]), "r"(a[1]), "r"(a[2]), "r"(a[3]),
          "r"(b[0]), "r"(b[1]));
}

__device__ __forceinline__ void cp_async16(uint32_t s, const void* g) {
    asm volatile("cp.async.cg.shared.global [%0], [%1], 16;\n" :: "r"(s), "l"(g));
}
__device__ __forceinline__ void cp_commit() {
    asm volatile("cp.async.commit_group;\n" ::: "memory");
}
template <int N>
__device__ __forceinline__ void cp_wait() {
    asm volatile("cp.async.wait_group %0;\n" :: "n"(N) : "memory");
}

__device__ __forceinline__ float gelu_exact(float x) {
    return 0.5f * x * (1.0f + erff(x * 0.7071067811865476f));
}

__global__ void round_tf32_kernel(const float* __restrict__ in,
                                  float* __restrict__ out, int n4) {
    int i = blockIdx.x * blockDim.x + threadIdx.x;
    if (i < n4) {
        float4 v = reinterpret_cast<const float4*>(in)[i];
        reinterpret_cast<float4*>(out)[i] =
            make_float4(tf32r(v.x), tf32r(v.y), tf32r(v.z), tf32r(v.w));
    }
}

__global__ void ln_kernel(const float* __restrict__ x,
                          const float* __restrict__ g,
                          const float* __restrict__ b,
                          float* __restrict__ out) {
    int row = blockIdx.x;
    int t   = threadIdx.x;
    const float4* xr = reinterpret_cast<const float4*>(x + (size_t)row * WIDTH);
    float4 v = xr[t];
    float s  = v.x + v.y + v.z + v.w;
    float ss = v.x*v.x + v.y*v.y + v.z*v.z + v.w*v.w;

    __shared__ float red_s[8], red_ss[8];
    float ws = warp_sum(s), wss = warp_sum(ss);
    int wid = t >> 5, lid = t & 31;
    if (lid == 0) { red_s[wid] = ws; red_ss[wid] = wss; }
    __syncthreads();
    if (wid == 0) {
        float a  = (lid < 8) ? red_s[lid]  : 0.f;
        float a2 = (lid < 8) ? red_ss[lid] : 0.f;
        a  = warp_sum(a);
        a2 = warp_sum(a2);
        if (lid == 0) { red_s[0] = a; red_ss[0] = a2; }
    }
    __syncthreads();
    float mu  = red_s[0]  * (1.0f / WIDTH);
    float var = red_ss[0] * (1.0f / WIDTH) - mu * mu;
    float rs  = rsqrtf(var + 1e-5f);

    const float4* g4 = reinterpret_cast<const float4*>(g);
    const float4* b4 = reinterpret_cast<const float4*>(b);
    float4 gg = g4[t], bb = b4[t];
    float4 o;
    o.x = tf32r((v.x - mu) * rs * gg.x + bb.x);
    o.y = tf32r((v.y - mu) * rs * gg.y + bb.y);
    o.z = tf32r((v.z - mu) * rs * gg.z + bb.z);
    o.w = tf32r((v.w - mu) * rs * gg.w + bb.w);
    reinterpret_cast<float4*>(out + (size_t)row * WIDTH)[t] = o;
}

// ---------------------------------------------------------------------------
// TF32 tensor-core GEMM, high-ILP config.
// BM=128, BN=256, BK=32, 256 threads = 8 warps (2x4), warp tile 64x64
// (4x8 m16n8k8 tiles = 32 independent accumulators per warp).
// 3-stage cp.async pipeline; register double-buffered fragments.
// As[m][k] stride 36 (bank = 4*gr+ctg), Bs[k][n] stride 264 (bank = 8*ctg+gr).
// OP: 0 none, 1 +bias+residual, 2 gelu(+bias). ROUND_OUT: tf32-round output.
// ---------------------------------------------------------------------------
#define SA 36
#define SB 264
#define AS_FLOATS (128 * SA)            // 4608
#define BS_FLOATS (32 * SB)             // 8448
#define STAGE_FLOATS (AS_FLOATS + BS_FLOATS)   // 13056
#define NSTAGE 3
#define GEMM_SMEM_BYTES (NSTAGE * STAGE_FLOATS * 4)   // 156672

template <int OP, int ROUND_OUT>
__global__ void __launch_bounds__(256)
gemm_tc(int M, int N, int K,
        const float* __restrict__ A,
        const float* __restrict__ B,
        const float* __restrict__ bias,
        const float* __restrict__ res,
        float* __restrict__ C) {
    extern __shared__ float sm[];

    const int tid     = threadIdx.x;
    const int warpId  = tid >> 5;
    const int lane    = tid & 31;
    const int gr      = lane >> 2;    // 0..7
    const int ctg     = lane & 3;     // 0..3
    const int warpRow = warpId >> 2;  // 0..1
    const int warpCol = warpId & 3;   // 0..3

    const int cRow = blockIdx.y;
    const int cCol = blockIdx.x;

    const float* Ablk = A + (size_t)cRow * 128 * K;
    const float* Bblk = B + cCol * 256;

    const uint32_t smBase = (uint32_t)__cvta_generic_to_shared(sm);

    auto load_stage = [&](int stg, int kb) {
        const uint32_t stageA = smBase + (uint32_t)(stg * STAGE_FLOATS) * 4u;
        const uint32_t stageB = stageA + (uint32_t)AS_FLOATS * 4u;
        const int kOff = kb << 5;
        // A: 128 rows x 32 floats = 1024 float4, 4 per thread
        #pragma unroll
        for (int i = 0; i < 4; i++) {
            int aIdx = tid + i * 256;
            int ar = aIdx >> 3, ac = (aIdx & 7) << 2;
            cp_async16(stageA + (uint32_t)(ar * SA + ac) * 4u,
                       Ablk + (size_t)ar * K + kOff + ac);
        }
        // B: 32 rows x 256 floats = 2048 float4, 8 per thread
        #pragma unroll
        for (int i = 0; i < 8; i++) {
            int bIdx = tid + i * 256;
            int br = bIdx >> 6, bc = (bIdx & 63) << 2;
            cp_async16(stageB + (uint32_t)(br * SB + bc) * 4u,
                       Bblk + (size_t)(kOff + br) * N + bc);
        }
    };

    float acc[4][8][4];
    #pragma unroll
    for (int i = 0; i < 4; i++)
        #pragma unroll
        for (int j = 0; j < 8; j++)
            #pragma unroll
            for (int k = 0; k < 4; k++) acc[i][j][k] = 0.f;

    const int nChunk = K >> 5;

    load_stage(0, 0); cp_commit();
    load_stage(1, 1); cp_commit();
    cp_wait<1>();
    __syncthreads();

    uint32_t afA[4][4], afB[4][4];     // double-buffered A frags
    uint32_t bfA[8][2], bfB[8][2];     // double-buffered B frags

    for (int kb = 0; kb < nChunk; kb++) {
        const int cur = kb % NSTAGE;
        if (kb + 2 < nChunk) load_stage((kb + 2) % NSTAGE, kb + 2);
        cp_commit();

        const uint32_t* uAs = reinterpret_cast<const uint32_t*>(sm + cur * STAGE_FLOATS);
        const uint32_t* uBs = uAs + AS_FLOATS;

        // preload frags for ks=0
        #pragma unroll
        for (int mt = 0; mt < 4; mt++) {
            const uint32_t* pa = uAs + (warpRow * 64 + mt * 16 + gr) * SA + ctg;
            afA[mt][0] = pa[0];
            afA[mt][1] = pa[8 * SA];
            afA[mt][2] = pa[4];
            afA[mt][3] = pa[8 * SA + 4];
        }
        #pragma unroll
        for (int nt = 0; nt < 8; nt++) {
            const uint32_t* pb = uBs + ctg * SB + warpCol * 64 + nt * 8 + gr;
            bfA[nt][0] = pb[0];
            bfA[nt][1] = pb[4 * SB];
        }

        #pragma unroll
        for (int ks = 0; ks < 4; ks++) {
            uint32_t (*afC)[4] = (ks & 1) ? afB : afA;
            uint32_t (*bfC)[2] = (ks & 1) ? bfB : bfA;
            uint32_t (*afN)[4] = (ks & 1) ? afA : afB;
            uint32_t (*bfN)[2] = (ks & 1) ? bfA : bfB;

            // prefetch frags for ks+1 BEFORE issuing mma for ks
            if (ks < 3) {
                #pragma unroll
                for (int mt = 0; mt < 4; mt++) {
                    const uint32_t* pa = uAs + (warpRow * 64 + mt * 16 + gr) * SA
                                       + (ks + 1) * 8 + ctg;
                    afN[mt][0] = pa[0];
                    afN[mt][1] = pa[8 * SA];
                    afN[mt][2] = pa[4];
                    afN[mt][3] = pa[8 * SA + 4];
                }
                #pragma unroll
                for (int nt = 0; nt < 8; nt++) {
                    const uint32_t* pb = uBs + ((ks + 1) * 8 + ctg) * SB
                                       + warpCol * 64 + nt * 8 + gr;
                    bfN[nt][0] = pb[0];
                    bfN[nt][1] = pb[4 * SB];
                }
            }

            #pragma unroll
            for (int mt = 0; mt < 4; mt++)
                #pragma unroll
                for (int nt = 0; nt < 8; nt++)
                    mma_tf32(acc[mt][nt], afC[mt], bfC[nt]);
        }

        cp_wait<1>();
        __syncthreads();
    }

    // --- epilogue ---
    #pragma unroll
    for (int mt = 0; mt < 4; mt++) {
        #pragma unroll
        for (int rr = 0; rr < 2; rr++) {
            const int row = cRow * 128 + warpRow * 64 + mt * 16 + gr + rr * 8;
            #pragma unroll
            for (int nt = 0; nt < 8; nt++) {
                const int col = cCol * 256 + warpCol * 64 + nt * 8 + 2 * ctg;
                float v0 = acc[mt][nt][rr * 2 + 0];
                float v1 = acc[mt][nt][rr * 2 + 1];
                if (OP == 1) {
                    float2 bi = *reinterpret_cast<const float2*>(bias + col);
                    float2 rv = *reinterpret_cast<const float2*>(res + (size_t)row * N + col);
                    v0 += bi.x + rv.x;
                    v1 += bi.y + rv.y;
                } else if (OP == 2) {
                    float2 bi = *reinterpret_cast<const float2*>(bias + col);
                    v0 = gelu_exact(v0 + bi.x);
                    v1 = gelu_exact(v1 + bi.y);
                }
                if (ROUND_OUT) { v0 = tf32r(v0); v1 = tf32r(v1); }
                *reinterpret_cast<float2*>(C + (size_t)row * N + col) = make_float2(v0, v1);
            }
        }
    }
}

// ---------------------------------------------------------------------------
// Flash attention with TF32 mma.sync (proven in R4, unchanged)
// ---------------------------------------------------------------------------
#define SATT 68
#define ATT_TILE (64 * SATT)
#define ATTN_SMEM_BYTES (4 * ATT_TILE * 4)

__global__ void __launch_bounds__(128)
attn_tc(const float* __restrict__ qkv, float* __restrict__ out) {
    extern __shared__ float sm[];
    float* Qs = sm;
    float* Ks = sm + ATT_TILE;
    float* Vs = sm + 2 * ATT_TILE;
    float* Ps = sm + 3 * ATT_TILE;
    const uint32_t* uQ = reinterpret_cast<const uint32_t*>(Qs);
    const uint32_t* uK = reinterpret_cast<const uint32_t*>(Ks);
    const uint32_t* uV = reinterpret_cast<const uint32_t*>(Vs);
    const uint32_t* uP = reinterpret_cast<const uint32_t*>(Ps);

    const int t     = threadIdx.x;
    const int warp  = t >> 5;
    const int lane  = t & 31;
    const int gr    = lane >> 2;
    const int ctg   = lane & 3;
    const int mbase = warp * 16;

    const int qb = blockIdx.x;
    const int bh = blockIdx.y;
    const int bb = bh >> 4;
    const int h  = bh & 15;
    const int tok0 = bb * SEQ;

    #pragma unroll
    for (int i = 0; i < 8; i++) {
        int idx = t + i * 128;
        int row = idx >> 4;
        int c   = (idx & 15) << 2;
        float4 v = *reinterpret_cast<const float4*>(
            qkv + (size_t)(tok0 + qb * 64 + row) * 3072 + h * 64 + c);
        *reinterpret_cast<float4*>(&Qs[row * SATT + c]) =
            make_float4(tf32r(v.x), tf32r(v.y), tf32r(v.z), tf32r(v.w));
    }

    float m0 = -1e30f, m1 = -1e30f, l0 = 0.f, l1 = 0.f;
    float o[8][4];
    #pragma unroll
    for (int nt = 0; nt < 8; nt++)
        #pragma unroll
        for (int k = 0; k < 4; k++) o[nt][k] = 0.f;

    for (int kb = 0; kb < SEQ / 64; kb++) {
        __syncthreads();

        #pragma unroll
        for (int i = 0; i < 8; i++) {
            int idx = t + i * 128;
            int row = idx >> 4;
            int c   = (idx & 15) << 2;
            const float* base = qkv + (size_t)(tok0 + kb * 64 + row) * 3072 + h * 64 + c;
            float4 kv = *reinterpret_cast<const float4*>(base + 1024);
            *reinterpret_cast<float4*>(&Ks[row * SATT + c]) =
                make_float4(tf32r(kv.x), tf32r(kv.y), tf32r(kv.z), tf32r(kv.w));
            float4 vv = *reinterpret_cast<const float4*>(base + 2048);
            *reinterpret_cast<float4*>(&Vs[row * SATT + c]) =
                make_float4(tf32r(vv.x), tf32r(vv.y), tf32r(vv.z), tf32r(vv.w));
        }
        __syncthreads();

        float s[8][4];
        #pragma unroll
        for (int nt = 0; nt < 8; nt++)
            #pragma unroll
            for (int k = 0; k < 4; k++) s[nt][k] = 0.f;

        #pragma unroll
        for (int ks = 0; ks < 8; ks++) {
            uint32_t af[4];
            const uint32_t* pa = uQ + (mbase + gr) * SATT + ks * 8 + ctg;
            af[0] = pa[0];
            af[1] = pa[8 * SATT];
            af[2] = pa[4];
            af[3] = pa[8 * SATT + 4];
            #pragma unroll
            for (int nt = 0; nt < 8; nt++) {
                uint32_t bf[2];
                const uint32_t* pb = uK + (nt * 8 + gr) * SATT + ks * 8 + ctg;
                bf[0] = pb[0];
                bf[1] = pb[4];
                mma_tf32(s[nt], af, bf);
            }
        }

        float mx0 = -1e30f, mx1 = -1e30f;
        #pragma unroll
        for (int nt = 0; nt < 8; nt++) {
            s[nt][0] *= 0.125f; s[nt][1] *= 0.125f;
            s[nt][2] *= 0.125f; s[nt][3] *= 0.125f;
            mx0 = fmaxf(mx0, fmaxf(s[nt][0], s[nt][1]));
            mx1 = fmaxf(mx1, fmaxf(s[nt][2], s[nt][3]));
        }
        mx0 = fmaxf(mx0, __shfl_xor_sync(0xffffffffu, mx0, 1));
        mx0 = fmaxf(mx0, __shfl_xor_sync(0xffffffffu, mx0, 2));
        mx1 = fmaxf(mx1, __shfl_xor_sync(0xffffffffu, mx1, 1));
        mx1 = fmaxf(mx1, __shfl_xor_sync(0xffffffffu, mx1, 2));

        float mn0 = fmaxf(m0, mx0), mn1 = fmaxf(m1, mx1);
        float corr0 = __expf(m0 - mn0), corr1 = __expf(m1 - mn1);
        float sum0 = 0.f, sum1 = 0.f;
        #pragma unroll
        for (int nt = 0; nt < 8; nt++) {
            s[nt][0] = __expf(s[nt][0] - mn0);
            s[nt][1] = __expf(s[nt][1] - mn0);
            s[nt][2] = __expf(s[nt][2] - mn1);
            s[nt][3] = __expf(s[nt][3] - mn1);
            sum0 += s[nt][0] + s[nt][1];
            sum1 += s[nt][2] + s[nt][3];
        }
        sum0 += __shfl_xor_sync(0xffffffffu, sum0, 1);
        sum0 += __shfl_xor_sync(0xffffffffu, sum0, 2);
        sum1 += __shfl_xor_sync(0xffffffffu, sum1, 1);
        sum1 += __shfl_xor_sync(0xffffffffu, sum1, 2);

        l0 = l0 * corr0 + sum0;  m0 = mn0;
        l1 = l1 * corr1 + sum1;  m1 = mn1;

        #pragma unroll
        for (int nt = 0; nt < 8; nt++) {
            o[nt][0] *= corr0; o[nt][1] *= corr0;
            o[nt][2] *= corr1; o[nt][3] *= corr1;
        }

        #pragma unroll
        for (int nt = 0; nt < 8; nt++) {
            *reinterpret_cast<float2*>(&Ps[(mbase + gr) * SATT + nt * 8 + 2 * ctg]) =
                make_float2(tf32r(s[nt][0]), tf32r(s[nt][1]));
            *reinterpret_cast<float2*>(&Ps[(mbase + gr + 8) * SATT + nt * 8 + 2 * ctg]) =
                make_float2(tf32r(s[nt][2]), tf32r(s[nt][3]));
        }
        __syncwarp();

        #pragma unroll
        for (int ks = 0; ks < 8; ks++) {
            uint32_t af[4];
            const uint32_t* pa = uP + (mbase + gr) * SATT + ks * 8 + ctg;
            af[0] = pa[0];
            af[1] = pa[8 * SATT];
            af[2] = pa[4];
            af[3] = pa[8 * SATT + 4];
            #pragma unroll
            for (int nt = 0; nt < 8; nt++) {
                uint32_t bf[2];
                const uint32_t* pb = uV + (ks * 8 + ctg) * SATT + nt * 8 + gr;
                bf[0] = pb[0];
                bf[1] = pb[4 * SATT];
                mma_tf32(o[nt], af, bf);
            }
        }
    }

    const float inv0 = 1.0f / l0, inv1 = 1.0f / l1;
    const int row0 = tok0 + qb * 64 + mbase + gr;
    #pragma unroll
    for (int nt = 0; nt < 8; nt++) {
        const int col = h * 64 + nt * 8 + 2 * ctg;
        *reinterpret_cast<float2*>(out + (size_t)row0 * WIDTH + col) =
            make_float2(tf32r(o[nt][0] * inv0), tf32r(o[nt][1] * inv0));
        *reinterpret_cast<float2*>(out + (size_t)(row0 + 8) * WIDTH + col) =
            make_float2(tf32r(o[nt][2] * inv1), tf32r(o[nt][3] * inv1));
    }
}

// ---------------------------------------------------------------------------
// Launch
// ---------------------------------------------------------------------------
extern "C" void kernel_launch(void* const* d_in, const int* in_sizes, int n_in,
                              void* d_out, int out_size) {
    const float* x      = (const float*)d_in[0];
    const float* ln1_g  = (const float*)d_in[1];
    const float* ln1_b  = (const float*)d_in[2];
    const float* w_qkv  = (const float*)d_in[3];
    const float* w_proj = (const float*)d_in[4];
    const float* b_proj = (const float*)d_in[5];
    const float* ln2_g  = (const float*)d_in[6];
    const float* ln2_b  = (const float*)d_in[7];
    const float* w_fc1  = (const float*)d_in[8];
    const float* b_fc1  = (const float*)d_in[9];
    const float* w_fc2  = (const float*)d_in[10];
    const float* b_fc2  = (const float*)d_in[11];
    float* out = (float*)d_out;

    void *ph, *pqkv, *pattn, *px1, *pfc1, *pwq, *pwp, *pw1, *pw2;
    cudaGetSymbolAddress(&ph,    g_h);
    cudaGetSymbolAddress(&pqkv,  g_qkv);
    cudaGetSymbolAddress(&pattn, g_attn);
    cudaGetSymbolAddress(&px1,   g_x1);
    cudaGetSymbolAddress(&pfc1,  g_fc1);
    cudaGetSymbolAddress(&pwq,   g_wqkv_r);
    cudaGetSymbolAddress(&pwp,   g_wproj_r);
    cudaGetSymbolAddress(&pw1,   g_wfc1_r);
    cudaGetSymbolAddress(&pw2,   g_wfc2_r);
    float* hbuf  = (float*)ph;
    float* qkvb  = (float*)pqkv;
    float* attnb = (float*)pattn;
    float* x1b   = (float*)px1;
    float* fc1b  = (float*)pfc1;
    float* wqr   = (float*)pwq;
    float* wpr   = (float*)pwp;
    float* w1r   = (float*)pw1;
    float* w2r   = (float*)pw2;

    cudaFuncSetAttribute(gemm_tc<0,0>, cudaFuncAttributeMaxDynamicSharedMemorySize, GEMM_SMEM_BYTES);
    cudaFuncSetAttribute(gemm_tc<1,0>, cudaFuncAttributeMaxDynamicSharedMemorySize, GEMM_SMEM_BYTES);
    cudaFuncSetAttribute(gemm_tc<2,1>, cudaFuncAttributeMaxDynamicSharedMemorySize, GEMM_SMEM_BYTES);
    cudaFuncSetAttribute(attn_tc,      cudaFuncAttributeMaxDynamicSharedMemorySize, ATTN_SMEM_BYTES);

    // 0) round weights to tf32
    {
        int n;
        n = WIDTH * 3 * WIDTH / 4;  round_tf32_kernel<<<(n + 255) / 256, 256>>>(w_qkv, wqr, n);
        n = WIDTH * WIDTH / 4;      round_tf32_kernel<<<(n + 255) / 256, 256>>>(w_proj, wpr, n);
        n = WIDTH * HIDDEN / 4;     round_tf32_kernel<<<(n + 255) / 256, 256>>>(w_fc1, w1r, n);
        n = HIDDEN * WIDTH / 4;     round_tf32_kernel<<<(n + 255) / 256, 256>>>(w_fc2, w2r, n);
    }

    // 1) LN1 (rounded output)
    ln_kernel<<<MTOK, 256>>>(x, ln1_g, ln1_b, hbuf);

    // 2) qkv = h @ w_qkv   [4096,1024]@[1024,3072]
    {
        dim3 grid(3 * WIDTH / 256, MTOK / 128);
        gemm_tc<0,0><<<grid, 256, GEMM_SMEM_BYTES>>>(MTOK, 3 * WIDTH, WIDTH,
                                                     hbuf, wqr, nullptr, nullptr, qkvb);
    }

    // 3) attention (rounded output)
    {
        dim3 grid(SEQ / 64, 2 * HEADS);
        attn_tc<<<grid, 128, ATTN_SMEM_BYTES>>>(qkvb, attnb);
    }

    // 4) x1 = x + attn @ w_proj + b_proj
    {
        dim3 grid(WIDTH / 256, MTOK / 128);
        gemm_tc<1,0><<<grid, 256, GEMM_SMEM_BYTES>>>(MTOK, WIDTH, WIDTH,
                                                     attnb, wpr, b_proj, x, x1b);
    }

    // 5) LN2 (rounded output)
    ln_kernel<<<MTOK, 256>>>(x1b, ln2_g, ln2_b, hbuf);

    // 6) fc1 = gelu(h @ w_fc1 + b_fc1) (rounded output)
    {
        dim3 grid(HIDDEN / 256, MTOK / 128);
        gemm_tc<2,1><<<grid, 256, GEMM_SMEM_BYTES>>>(MTOK, HIDDEN, WIDTH,
                                                     hbuf, w1r, b_fc1, nullptr, fc1b);
    }

    // 7) out = x1 + fc1 @ w_fc2 + b_fc2
    {
        dim3 grid(WIDTH / 256, MTOK / 128);
        gemm_tc<1,0><<<grid, 256, GEMM_SMEM_BYTES>>>(MTOK, WIDTH, HIDDEN,
                                                     fc1b, w2r, b_fc2, x1b, out);
    }
}

// round 8
// speedup vs baseline: 1.0312x; 1.0312x over previous
#include <cuda_runtime.h>
#include <cuda_bf16.h>
#include <math.h>
#include <stdint.h>

#define MTOK   4096
#define WIDTH  1024
#define HEADS  16
#define HDIM   64
#define HIDDEN 4096
#define SEQ    2048

__device__ float g_h   [MTOK * WIDTH];
__device__ float g_qkv [MTOK * 3 * WIDTH];
__device__ float g_attn[MTOK * WIDTH];
__device__ float g_x1  [MTOK * WIDTH];
__device__ float g_fc1 [MTOK * HIDDEN];
__device__ float g_wqkv_r [WIDTH * 3 * WIDTH];
__device__ float g_wproj_r[WIDTH * WIDTH];
__device__ float g_wfc1_r [WIDTH * HIDDEN];
__device__ float g_wfc2_r [HIDDEN * WIDTH];

__device__ __forceinline__ float warp_sum(float v) {
    #pragma unroll
    for (int o = 16; o > 0; o >>= 1) v += __shfl_xor_sync(0xffffffffu, v, o);
    return v;
}

__device__ __forceinline__ float tf32r(float x) {
    uint32_t u;
    asm("cvt.rna.tf32.f32 %0, %1;" : "=r"(u) : "f"(x));
    return __uint_as_float(u);
}

__device__ __forceinline__ void mma_tf32(float c[4], const uint32_t a[4], const uint32_t b[2]) {
    asm volatile(
        "mma.sync.aligned.m16n8k8.row.col.f32.tf32.tf32.f32 "
        "{%0,%1,%2,%3}, {%4,%5,%6,%7}, {%8,%9}, {%0,%1,%2,%3};\n"
        : "+f"(c[0]), "+f"(c[1]), "+f"(c[2]), "+f"(c[3])
        : "r"(a[0]), "r"(a[1]), "r"(a[2]), "r"(a[3]),
          "r"(b[0]), "r"(b[1]));
}

__device__ __forceinline__ void cp_async16(uint32_t s, const void* g) {
    asm volatile("cp.async.cg.shared.global [%0], [%1], 16;\n" :: "r"(s), "l"(g));
}
__device__ __forceinline__ void cp_commit() {
    asm volatile("cp.async.commit_group;\n" ::: "memory");
}
template <int N>
__device__ __forceinline__ void cp_wait() {
    asm volatile("cp.async.wait_group %0;\n" :: "n"(N) : "memory");
}

__device__ __forceinline__ float gelu_exact(float x) {
    return 0.5f * x * (1.0f + erff(x * 0.7071067811865476f));
}

__global__ void round_tf32_kernel(const float* __restrict__ in,
                                  float* __restrict__ out, int n4) {
    int i = blockIdx.x * blockDim.x + threadIdx.x;
    if (i < n4) {
        float4 v = reinterpret_cast<const float4*>(in)[i];
        reinterpret_cast<float4*>(out)[i] =
            make_float4(tf32r(v.x), tf32r(v.y), tf32r(v.z), tf32r(v.w));
    }
}

__global__ void ln_kernel(const float* __restrict__ x,
                          const float* __restrict__ g,
                          const float* __restrict__ b,
                          float* __restrict__ out) {
    int row = blockIdx.x;
    int t   = threadIdx.x;
    const float4* xr = reinterpret_cast<const float4*>(x + (size_t)row * WIDTH);
    float4 v = xr[t];
    float s  = v.x + v.y + v.z + v.w;
    float ss = v.x*v.x + v.y*v.y + v.z*v.z + v.w*v.w;

    __shared__ float red_s[8], red_ss[8];
    float ws = warp_sum(s), wss = warp_sum(ss);
    int wid = t >> 5, lid = t & 31;
    if (lid == 0) { red_s[wid] = ws; red_ss[wid] = wss; }
    __syncthreads();
    if (wid == 0) {
        float a  = (lid < 8) ? red_s[lid]  : 0.f;
        float a2 = (lid < 8) ? red_ss[lid] : 0.f;
        a  = warp_sum(a);
        a2 = warp_sum(a2);
        if (lid == 0) { red_s[0] = a; red_ss[0] = a2; }
    }
    __syncthreads();
    float mu  = red_s[0]  * (1.0f / WIDTH);
    float var = red_ss[0] * (1.0f / WIDTH) - mu * mu;
    float rs  = rsqrtf(var + 1e-5f);

    const float4* g4 = reinterpret_cast<const float4*>(g);
    const float4* b4 = reinterpret_cast<const float4*>(b);
    float4 gg = g4[t], bb = b4[t];
    float4 o;
    o.x = tf32r((v.x - mu) * rs * gg.x + bb.x);
    o.y = tf32r((v.y - mu) * rs * gg.y + bb.y);
    o.z = tf32r((v.z - mu) * rs * gg.z + bb.z);
    o.w = tf32r((v.w - mu) * rs * gg.w + bb.w);
    reinterpret_cast<float4*>(out + (size_t)row * WIDTH)[t] = o;
}

// ---------------------------------------------------------------------------
// TF32 tensor-core GEMM (exact R4 config: BM=BN=128, BK=32, 2 CTAs/SM,
// 3-stage cp.async). OP: 0 none, 1 +bias+residual, 2 gelu(+bias).
// ---------------------------------------------------------------------------
#define SA 36
#define SB 136
#define AS_FLOATS (128 * SA)
#define BS_FLOATS (32 * SB)
#define STAGE_FLOATS (AS_FLOATS + BS_FLOATS)
#define NSTAGE 3
#define GEMM_SMEM_BYTES (NSTAGE * STAGE_FLOATS * 4)

template <int OP, int ROUND_OUT>
__global__ void __launch_bounds__(256, 2)
gemm_tc(int M, int N, int K,
        const float* __restrict__ A,
        const float* __restrict__ B,
        const float* __restrict__ bias,
        const float* __restrict__ res,
        float* __restrict__ C) {
    extern __shared__ float sm[];

    const int tid     = threadIdx.x;
    const int warpId  = tid >> 5;
    const int lane    = tid & 31;
    const int gr      = lane >> 2;
    const int ctg     = lane & 3;
    const int warpRow = warpId >> 2;
    const int warpCol = warpId & 3;

    const int cRow = blockIdx.y;
    const int cCol = blockIdx.x;

    const float* Ablk = A + (size_t)cRow * 128 * K;
    const float* Bblk = B + cCol * 128;

    const uint32_t smBase = (uint32_t)__cvta_generic_to_shared(sm);

    auto load_stage = [&](int stg, int kb) {
        const uint32_t stageA = smBase + (uint32_t)(stg * STAGE_FLOATS) * 4u;
        const uint32_t stageB = stageA + (uint32_t)AS_FLOATS * 4u;
        const int kOff = kb << 5;
        #pragma unroll
        for (int i = 0; i < 4; i++) {
            int aIdx = tid + i * 256;
            int ar = aIdx >> 3, ac = (aIdx & 7) << 2;
            cp_async16(stageA + (uint32_t)(ar * SA + ac) * 4u,
                       Ablk + (size_t)ar * K + kOff + ac);
            int bIdx = tid + i * 256;
            int br = bIdx >> 5, bc = (bIdx & 31) << 2;
            cp_async16(stageB + (uint32_t)(br * SB + bc) * 4u,
                       Bblk + (size_t)(kOff + br) * N + bc);
        }
    };

    float acc[4][4][4];
    #pragma unroll
    for (int i = 0; i < 4; i++)
        #pragma unroll
        for (int j = 0; j < 4; j++)
            #pragma unroll
            for (int k = 0; k < 4; k++) acc[i][j][k] = 0.f;

    const int nChunk = K >> 5;

    load_stage(0, 0); cp_commit();
    load_stage(1, 1); cp_commit();
    cp_wait<1>();
    __syncthreads();

    for (int kb = 0; kb < nChunk; kb++) {
        const int cur = kb % NSTAGE;
        if (kb + 2 < nChunk) load_stage((kb + 2) % NSTAGE, kb + 2);
        cp_commit();

        const uint32_t* uAs = reinterpret_cast<const uint32_t*>(sm + cur * STAGE_FLOATS);
        const uint32_t* uBs = uAs + AS_FLOATS;

        #pragma unroll
        for (int ks = 0; ks < 4; ks++) {
            uint32_t af[4][4];
            #pragma unroll
            for (int mt = 0; mt < 4; mt++) {
                int m0 = warpRow * 64 + mt * 16 + gr;
                const uint32_t* pa = uAs + m0 * SA + ks * 8 + ctg;
                af[mt][0] = pa[0];
                af[mt][1] = pa[8 * SA];
                af[mt][2] = pa[4];
                af[mt][3] = pa[8 * SA + 4];
            }
            uint32_t bf[4][2];
            #pragma unroll
            for (int nt = 0; nt < 4; nt++) {
                int nb = warpCol * 32 + nt * 8 + gr;
                const uint32_t* pb = uBs + (ks * 8 + ctg) * SB + nb;
                bf[nt][0] = pb[0];
                bf[nt][1] = pb[4 * SB];
            }
            #pragma unroll
            for (int mt = 0; mt < 4; mt++)
                #pragma unroll
                for (int nt = 0; nt < 4; nt++)
                    mma_tf32(acc[mt][nt], af[mt], bf[nt]);
        }

        cp_wait<1>();
        __syncthreads();
    }

    #pragma unroll
    for (int mt = 0; mt < 4; mt++) {
        #pragma unroll
        for (int rr = 0; rr < 2; rr++) {
            const int row = cRow * 128 + warpRow * 64 + mt * 16 + gr + rr * 8;
            #pragma unroll
            for (int nt = 0; nt < 4; nt++) {
                const int col = cCol * 128 + warpCol * 32 + nt * 8 + 2 * ctg;
                float v0 = acc[mt][nt][rr * 2 + 0];
                float v1 = acc[mt][nt][rr * 2 + 1];
                if (OP == 1) {
                    float2 bi = *reinterpret_cast<const float2*>(bias + col);
                    float2 rv = *reinterpret_cast<const float2*>(res + (size_t)row * N + col);
                    v0 += bi.x + rv.x;
                    v1 += bi.y + rv.y;
                } else if (OP == 2) {
                    float2 bi = *reinterpret_cast<const float2*>(bias + col);
                    v0 = gelu_exact(v0 + bi.x);
                    v1 = gelu_exact(v1 + bi.y);
                }
                if (ROUND_OUT) { v0 = tf32r(v0); v1 = tf32r(v1); }
                *reinterpret_cast<float2*>(C + (size_t)row * N + col) = make_float2(v0, v1);
            }
        }
    }
}

// ---------------------------------------------------------------------------
// Flash attention, BQ=128 queries per block (8 warps / 256 threads).
// qkv arrives tf32-pre-rounded (qkv GEMM ROUND_OUT=1) -> raw float4 loads,
// no cvt in the hot loop. Warp w owns query rows [16w,16w+16): stats in regs.
// Smem: Qs[128][68], Ks[64][68], Vs[64][68], Ps[128][68].
// ---------------------------------------------------------------------------
#define SATT 68
#define Q_TILE (128 * SATT)
#define KV_TILE (64 * SATT)
#define ATTN_SMEM_BYTES ((Q_TILE + 2 * KV_TILE + Q_TILE) * 4)   // 104448

__global__ void __launch_bounds__(256)
attn_tc(const float* __restrict__ qkv, float* __restrict__ out) {
    extern __shared__ float sm[];
    float* Qs = sm;                       // [128][68]
    float* Ks = Qs + Q_TILE;              // [64][68]
    float* Vs = Ks + KV_TILE;             // [64][68]
    float* Ps = Vs + KV_TILE;             // [128][68]
    const uint32_t* uQ = reinterpret_cast<const uint32_t*>(Qs);
    const uint32_t* uK = reinterpret_cast<const uint32_t*>(Ks);
    const uint32_t* uV = reinterpret_cast<const uint32_t*>(Vs);
    const uint32_t* uP = reinterpret_cast<const uint32_t*>(Ps);

    const int t     = threadIdx.x;
    const int warp  = t >> 5;             // 0..7
    const int lane  = t & 31;
    const int gr    = lane >> 2;
    const int ctg   = lane & 3;
    const int mbase = warp * 16;

    const int qb = blockIdx.x;            // 0..15 (128-query blocks)
    const int bh = blockIdx.y;
    const int bb = bh >> 4;
    const int h  = bh & 15;
    const int tok0 = bb * SEQ;

    // ---- load Q tile: 128 rows x 64 cols, raw (pre-rounded) ----
    #pragma unroll
    for (int i = 0; i < 8; i++) {
        int idx = t + i * 256;            // 0..2047
        int row = idx >> 4;
        int c   = (idx & 15) << 2;
        *reinterpret_cast<float4*>(&Qs[row * SATT + c]) =
            *reinterpret_cast<const float4*>(
                qkv + (size_t)(tok0 + qb * 128 + row) * 3072 + h * 64 + c);
    }

    float m0 = -1e30f, m1 = -1e30f, l0 = 0.f, l1 = 0.f;
    float o[8][4];
    #pragma unroll
    for (int nt = 0; nt < 8; nt++)
        #pragma unroll
        for (int k = 0; k < 4; k++) o[nt][k] = 0.f;

    for (int kb = 0; kb < SEQ / 64; kb++) {
        __syncthreads();

        // ---- load K, V tiles: 64 rows x 64 cols each ----
        #pragma unroll
        for (int i = 0; i < 4; i++) {
            int idx = t + i * 256;        // 0..1023
            int row = idx >> 4;
            int c   = (idx & 15) << 2;
            const float* base = qkv + (size_t)(tok0 + kb * 64 + row) * 3072 + h * 64 + c;
            *reinterpret_cast<float4*>(&Ks[row * SATT + c]) =
                *reinterpret_cast<const float4*>(base + 1024);
            *reinterpret_cast<float4*>(&Vs[row * SATT + c]) =
                *reinterpret_cast<const float4*>(base + 2048);
        }
        __syncthreads();

        // ---- S = Q K^T ----
        float s[8][4];
        #pragma unroll
        for (int nt = 0; nt < 8; nt++)
            #pragma unroll
            for (int k = 0; k < 4; k++) s[nt][k] = 0.f;

        #pragma unroll
        for (int ks = 0; ks < 8; ks++) {
            uint32_t af[4];
            const uint32_t* pa = uQ + (mbase + gr) * SATT + ks * 8 + ctg;
            af[0] = pa[0];
            af[1] = pa[8 * SATT];
            af[2] = pa[4];
            af[3] = pa[8 * SATT + 4];
            #pragma unroll
            for (int nt = 0; nt < 8; nt++) {
                uint32_t bf[2];
                const uint32_t* pb = uK + (nt * 8 + gr) * SATT + ks * 8 + ctg;
                bf[0] = pb[0];
                bf[1] = pb[4];
                mma_tf32(s[nt], af, bf);
            }
        }

        // ---- online softmax ----
        float mx0 = -1e30f, mx1 = -1e30f;
        #pragma unroll
        for (int nt = 0; nt < 8; nt++) {
            s[nt][0] *= 0.125f; s[nt][1] *= 0.125f;
            s[nt][2] *= 0.125f; s[nt][3] *= 0.125f;
            mx0 = fmaxf(mx0, fmaxf(s[nt][0], s[nt][1]));
            mx1 = fmaxf(mx1, fmaxf(s[nt][2], s[nt][3]));
        }
        mx0 = fmaxf(mx0, __shfl_xor_sync(0xffffffffu, mx0, 1));
        mx0 = fmaxf(mx0, __shfl_xor_sync(0xffffffffu, mx0, 2));
        mx1 = fmaxf(mx1, __shfl_xor_sync(0xffffffffu, mx1, 1));
        mx1 = fmaxf(mx1, __shfl_xor_sync(0xffffffffu, mx1, 2));

        float mn0 = fmaxf(m0, mx0), mn1 = fmaxf(m1, mx1);
        float corr0 = __expf(m0 - mn0), corr1 = __expf(m1 - mn1);
        float sum0 = 0.f, sum1 = 0.f;
        #pragma unroll
        for (int nt = 0; nt < 8; nt++) {
            s[nt][0] = __expf(s[nt][0] - mn0);
            s[nt][1] = __expf(s[nt][1] - mn0);
            s[nt][2] = __expf(s[nt][2] - mn1);
            s[nt][3] = __expf(s[nt][3] - mn1);
            sum0 += s[nt][0] + s[nt][1];
            sum1 += s[nt][2] + s[nt][3];
        }
        sum0 += __shfl_xor_sync(0xffffffffu, sum0, 1);
        sum0 += __shfl_xor_sync(0xffffffffu, sum0, 2);
        sum1 += __shfl_xor_sync(0xffffffffu, sum1, 1);
        sum1 += __shfl_xor_sync(0xffffffffu, sum1, 2);

        l0 = l0 * corr0 + sum0;  m0 = mn0;
        l1 = l1 * corr1 + sum1;  m1 = mn1;

        #pragma unroll
        for (int nt = 0; nt < 8; nt++) {
            o[nt][0] *= corr0; o[nt][1] *= corr0;
            o[nt][2] *= corr1; o[nt][3] *= corr1;
        }

        // ---- store P (warp-private rows), tf32-rounded ----
        #pragma unroll
        for (int nt = 0; nt < 8; nt++) {
            *reinterpret_cast<float2*>(&Ps[(mbase + gr) * SATT + nt * 8 + 2 * ctg]) =
                make_float2(tf32r(s[nt][0]), tf32r(s[nt][1]));
            *reinterpret_cast<float2*>(&Ps[(mbase + gr + 8) * SATT + nt * 8 + 2 * ctg]) =
                make_float2(tf32r(s[nt][2]), tf32r(s[nt][3]));
        }
        __syncwarp();

        // ---- O += P V ----
        #pragma unroll
        for (int ks = 0; ks < 8; ks++) {
            uint32_t af[4];
            const uint32_t* pa = uP + (mbase + gr) * SATT + ks * 8 + ctg;
            af[0] = pa[0];
            af[1] = pa[8 * SATT];
            af[2] = pa[4];
            af[3] = pa[8 * SATT + 4];
            #pragma unroll
            for (int nt = 0; nt < 8; nt++) {
                uint32_t bf[2];
                const uint32_t* pb = uV + (ks * 8 + ctg) * SATT + nt * 8 + gr;
                bf[0] = pb[0];
                bf[1] = pb[4 * SATT];
                mma_tf32(o[nt], af, bf);
            }
        }
    }

    // ---- final normalize + store (rounded: feeds proj GEMM A operand) ----
    const float inv0 = 1.0f / l0, inv1 = 1.0f / l1;
    const int row0 = tok0 + qb * 128 + mbase + gr;
    #pragma unroll
    for (int nt = 0; nt < 8; nt++) {
        const int col = h * 64 + nt * 8 + 2 * ctg;
        *reinterpret_cast<float2*>(out + (size_t)row0 * WIDTH + col) =
            make_float2(tf32r(o[nt][0] * inv0), tf32r(o[nt][1] * inv0));
        *reinterpret_cast<float2*>(out + (size_t)(row0 + 8) * WIDTH + col) =
            make_float2(tf32r(o[nt][2] * inv1), tf32r(o[nt][3] * inv1));
    }
}

// ---------------------------------------------------------------------------
// Launch
// ---------------------------------------------------------------------------
extern "C" void kernel_launch(void* const* d_in, const int* in_sizes, int n_in,
                              void* d_out, int out_size) {
    const float* x      = (const float*)d_in[0];
    const float* ln1_g  = (const float*)d_in[1];
    const float* ln1_b  = (const float*)d_in[2];
    const float* w_qkv  = (const float*)d_in[3];
    const float* w_proj = (const float*)d_in[4];
    const float* b_proj = (const float*)d_in[5];
    const float* ln2_g  = (const float*)d_in[6];
    const float* ln2_b  = (const float*)d_in[7];
    const float* w_fc1  = (const float*)d_in[8];
    const float* b_fc1  = (const float*)d_in[9];
    const float* w_fc2  = (const float*)d_in[10];
    const float* b_fc2  = (const float*)d_in[11];
    float* out = (float*)d_out;

    void *ph, *pqkv, *pattn, *px1, *pfc1, *pwq, *pwp, *pw1, *pw2;
    cudaGetSymbolAddress(&ph,    g_h);
    cudaGetSymbolAddress(&pqkv,  g_qkv);
    cudaGetSymbolAddress(&pattn, g_attn);
    cudaGetSymbolAddress(&px1,   g_x1);
    cudaGetSymbolAddress(&pfc1,  g_fc1);
    cudaGetSymbolAddress(&pwq,   g_wqkv_r);
    cudaGetSymbolAddress(&pwp,   g_wproj_r);
    cudaGetSymbolAddress(&pw1,   g_wfc1_r);
    cudaGetSymbolAddress(&pw2,   g_wfc2_r);
    float* hbuf  = (float*)ph;
    float* qkvb  = (float*)pqkv;
    float* attnb = (float*)pattn;
    float* x1b   = (float*)px1;
    float* fc1b  = (float*)pfc1;
    float* wqr   = (float*)pwq;
    float* wpr   = (float*)pwp;
    float* w1r   = (float*)pw1;
    float* w2r   = (float*)pw2;

    cudaFuncSetAttribute(gemm_tc<0,1>, cudaFuncAttributeMaxDynamicSharedMemorySize, GEMM_SMEM_BYTES);
    cudaFuncSetAttribute(gemm_tc<1,0>, cudaFuncAttributeMaxDynamicSharedMemorySize, GEMM_SMEM_BYTES);
    cudaFuncSetAttribute(gemm_tc<2,1>, cudaFuncAttributeMaxDynamicSharedMemorySize, GEMM_SMEM_BYTES);
    cudaFuncSetAttribute(attn_tc,      cudaFuncAttributeMaxDynamicSharedMemorySize, ATTN_SMEM_BYTES);

    // 0) round weights to tf32
    {
        int n;
        n = WIDTH * 3 * WIDTH / 4;  round_tf32_kernel<<<(n + 255) / 256, 256>>>(w_qkv, wqr, n);
        n = WIDTH * WIDTH / 4;      round_tf32_kernel<<<(n + 255) / 256, 256>>>(w_proj, wpr, n);
        n = WIDTH * HIDDEN / 4;     round_tf32_kernel<<<(n + 255) / 256, 256>>>(w_fc1, w1r, n);
        n = HIDDEN * WIDTH / 4;     round_tf32_kernel<<<(n + 255) / 256, 256>>>(w_fc2, w2r, n);
    }

    // 1) LN1 (rounded output)
    ln_kernel<<<MTOK, 256>>>(x, ln1_g, ln1_b, hbuf);

    // 2) qkv = h @ w_qkv (ROUNDED output -> attention loads raw bits)
    {
        dim3 grid(3 * WIDTH / 128, MTOK / 128);
        gemm_tc<0,1><<<grid, 256, GEMM_SMEM_BYTES>>>(MTOK, 3 * WIDTH, WIDTH,
                                                     hbuf, wqr, nullptr, nullptr, qkvb);
    }

    // 3) attention (rounded output, 128-query blocks)
    {
        dim3 grid(SEQ / 128, 2 * HEADS);
        attn_tc<<<grid, 256, ATTN_SMEM_BYTES>>>(qkvb, attnb);
    }

    // 4) x1 = x + attn @ w_proj + b_proj
    {
        dim3 grid(WIDTH / 128, MTOK / 128);
        gemm_tc<1,0><<<grid, 256, GEMM_SMEM_BYTES>>>(MTOK, WIDTH, WIDTH,
                                                     attnb, wpr, b_proj, x, x1b);
    }

    // 5) LN2 (rounded output)
    ln_kernel<<<MTOK, 256>>>(x1b, ln2_g, ln2_b, hbuf);

    // 6) fc1 = gelu(h @ w_fc1 + b_fc1) (rounded output)
    {
        dim3 grid(HIDDEN / 128, MTOK / 128);
        gemm_tc<2,1><<<grid, 256, GEMM_SMEM_BYTES>>>(MTOK, HIDDEN, WIDTH,
                                                     hbuf, w1r, b_fc1, nullptr, fc1b);
    }

    // 7) out = x1 + fc1 @ w_fc2 + b_fc2
    {
        dim3 grid(WIDTH / 128, MTOK / 128);
        gemm_tc<1,0><<<grid, 256, GEMM_SMEM_BYTES>>>(MTOK, WIDTH, HIDDEN,
                                                     fc1b, w2r, b_fc2, x1b, out);
    }
}

// round 9
// speedup vs baseline: 1.0717x; 1.0394x over previous
#include <cuda_runtime.h>
#include <cuda_bf16.h>
#include <math.h>
#include <stdint.h>

#define MTOK   4096
#define WIDTH  1024
#define HEADS  16
#define HDIM   64
#define HIDDEN 4096
#define SEQ    2048

__device__ float g_h   [MTOK * WIDTH];
__device__ float g_qkv [MTOK * 3 * WIDTH];
__device__ float g_attn[MTOK * WIDTH];
__device__ float g_x1  [MTOK * WIDTH];
__device__ float g_fc1 [MTOK * HIDDEN];
__device__ float g_wqkv_r [WIDTH * 3 * WIDTH];
__device__ float g_wproj_r[WIDTH * WIDTH];
__device__ float g_wfc1_r [WIDTH * HIDDEN];
__device__ float g_wfc2_r [HIDDEN * WIDTH];

__device__ __forceinline__ float warp_sum(float v) {
    #pragma unroll
    for (int o = 16; o > 0; o >>= 1) v += __shfl_xor_sync(0xffffffffu, v, o);
    return v;
}

__device__ __forceinline__ float tf32r(float x) {
    uint32_t u;
    asm("cvt.rna.tf32.f32 %0, %1;" : "=r"(u) : "f"(x));
    return __uint_as_float(u);
}

__device__ __forceinline__ void mma_tf32(float c[4], const uint32_t a[4], const uint32_t b[2]) {
    asm volatile(
        "mma.sync.aligned.m16n8k8.row.col.f32.tf32.tf32.f32 "
        "{%0,%1,%2,%3}, {%4,%5,%6,%7}, {%8,%9}, {%0,%1,%2,%3};\n"
        : "+f"(c[0]), "+f"(c[1]), "+f"(c[2]), "+f"(c[3])
        : "r"(a[0]), "r"(a[1]), "r"(a[2]), "r"(a[3]),
          "r"(b[0]), "r"(b[1]));
}

__device__ __forceinline__ void cp_async16(uint32_t s, const void* g) {
    asm volatile("cp.async.cg.shared.global [%0], [%1], 16;\n" :: "r"(s), "l"(g));
}
__device__ __forceinline__ void cp_commit() {
    asm volatile("cp.async.commit_group;\n" ::: "memory");
}
template <int N>
__device__ __forceinline__ void cp_wait() {
    asm volatile("cp.async.wait_group %0;\n" :: "n"(N) : "memory");
}

__device__ __forceinline__ float gelu_exact(float x) {
    return 0.5f * x * (1.0f + erff(x * 0.7071067811865476f));
}

// 4 coalesced float4 per thread; n4 must be divisible by 1024 (all ours are).
__global__ void round_tf32_kernel(const float* __restrict__ in,
                                  float* __restrict__ out, int n4) {
    int base = blockIdx.x * 1024 + threadIdx.x;
    #pragma unroll
    for (int i = 0; i < 4; i++) {
        int idx = base + i * 256;
        float4 v = reinterpret_cast<const float4*>(in)[idx];
        reinterpret_cast<float4*>(out)[idx] =
            make_float4(tf32r(v.x), tf32r(v.y), tf32r(v.z), tf32r(v.w));
    }
}

__global__ void ln_kernel(const float* __restrict__ x,
                          const float* __restrict__ g,
                          const float* __restrict__ b,
                          float* __restrict__ out) {
    int row = blockIdx.x;
    int t   = threadIdx.x;
    const float4* xr = reinterpret_cast<const float4*>(x + (size_t)row * WIDTH);
    float4 v = xr[t];
    float s  = v.x + v.y + v.z + v.w;
    float ss = v.x*v.x + v.y*v.y + v.z*v.z + v.w*v.w;

    __shared__ float red_s[8], red_ss[8];
    float ws = warp_sum(s), wss = warp_sum(ss);
    int wid = t >> 5, lid = t & 31;
    if (lid == 0) { red_s[wid] = ws; red_ss[wid] = wss; }
    __syncthreads();
    if (wid == 0) {
        float a  = (lid < 8) ? red_s[lid]  : 0.f;
        float a2 = (lid < 8) ? red_ss[lid] : 0.f;
        a  = warp_sum(a);
        a2 = warp_sum(a2);
        if (lid == 0) { red_s[0] = a; red_ss[0] = a2; }
    }
    __syncthreads();
    float mu  = red_s[0]  * (1.0f / WIDTH);
    float var = red_ss[0] * (1.0f / WIDTH) - mu * mu;
    float rs  = rsqrtf(var + 1e-5f);

    const float4* g4 = reinterpret_cast<const float4*>(g);
    const float4* b4 = reinterpret_cast<const float4*>(b);
    float4 gg = g4[t], bb = b4[t];
    float4 o;
    o.x = tf32r((v.x - mu) * rs * gg.x + bb.x);
    o.y = tf32r((v.y - mu) * rs * gg.y + bb.y);
    o.z = tf32r((v.z - mu) * rs * gg.z + bb.z);
    o.w = tf32r((v.w - mu) * rs * gg.w + bb.w);
    reinterpret_cast<float4*>(out + (size_t)row * WIDTH)[t] = o;
}

// ---------------------------------------------------------------------------
// TF32 tensor-core GEMM (exact R4 config: BM=BN=128, BK=32, 2 CTAs/SM,
// 3-stage cp.async). OP: 0 none, 1 +bias+residual, 2 gelu(+bias).
// ---------------------------------------------------------------------------
#define SA 36
#define SB 136
#define AS_FLOATS (128 * SA)
#define BS_FLOATS (32 * SB)
#define STAGE_FLOATS (AS_FLOATS + BS_FLOATS)
#define NSTAGE 3
#define GEMM_SMEM_BYTES (NSTAGE * STAGE_FLOATS * 4)

template <int OP, int ROUND_OUT>
__global__ void __launch_bounds__(256, 2)
gemm_tc(int M, int N, int K,
        const float* __restrict__ A,
        const float* __restrict__ B,
        const float* __restrict__ bias,
        const float* __restrict__ res,
        float* __restrict__ C) {
    extern __shared__ float sm[];

    const int tid     = threadIdx.x;
    const int warpId  = tid >> 5;
    const int lane    = tid & 31;
    const int gr      = lane >> 2;
    const int ctg     = lane & 3;
    const int warpRow = warpId >> 2;
    const int warpCol = warpId & 3;

    const int cRow = blockIdx.y;
    const int cCol = blockIdx.x;

    const float* Ablk = A + (size_t)cRow * 128 * K;
    const float* Bblk = B + cCol * 128;

    const uint32_t smBase = (uint32_t)__cvta_generic_to_shared(sm);

    auto load_stage = [&](int stg, int kb) {
        const uint32_t stageA = smBase + (uint32_t)(stg * STAGE_FLOATS) * 4u;
        const uint32_t stageB = stageA + (uint32_t)AS_FLOATS * 4u;
        const int kOff = kb << 5;
        #pragma unroll
        for (int i = 0; i < 4; i++) {
            int aIdx = tid + i * 256;
            int ar = aIdx >> 3, ac = (aIdx & 7) << 2;
            cp_async16(stageA + (uint32_t)(ar * SA + ac) * 4u,
                       Ablk + (size_t)ar * K + kOff + ac);
            int bIdx = tid + i * 256;
            int br = bIdx >> 5, bc = (bIdx & 31) << 2;
            cp_async16(stageB + (uint32_t)(br * SB + bc) * 4u,
                       Bblk + (size_t)(kOff + br) * N + bc);
        }
    };

    float acc[4][4][4];
    #pragma unroll
    for (int i = 0; i < 4; i++)
        #pragma unroll
        for (int j = 0; j < 4; j++)
            #pragma unroll
            for (int k = 0; k < 4; k++) acc[i][j][k] = 0.f;

    const int nChunk = K >> 5;

    load_stage(0, 0); cp_commit();
    load_stage(1, 1); cp_commit();
    cp_wait<1>();
    __syncthreads();

    for (int kb = 0; kb < nChunk; kb++) {
        const int cur = kb % NSTAGE;
        if (kb + 2 < nChunk) load_stage((kb + 2) % NSTAGE, kb + 2);
        cp_commit();

        const uint32_t* uAs = reinterpret_cast<const uint32_t*>(sm + cur * STAGE_FLOATS);
        const uint32_t* uBs = uAs + AS_FLOATS;

        #pragma unroll
        for (int ks = 0; ks < 4; ks++) {
            uint32_t af[4][4];
            #pragma unroll
            for (int mt = 0; mt < 4; mt++) {
                int m0 = warpRow * 64 + mt * 16 + gr;
                const uint32_t* pa = uAs + m0 * SA + ks * 8 + ctg;
                af[mt][0] = pa[0];
                af[mt][1] = pa[8 * SA];
                af[mt][2] = pa[4];
                af[mt][3] = pa[8 * SA + 4];
            }
            uint32_t bf[4][2];
            #pragma unroll
            for (int nt = 0; nt < 4; nt++) {
                int nb = warpCol * 32 + nt * 8 + gr;
                const uint32_t* pb = uBs + (ks * 8 + ctg) * SB + nb;
                bf[nt][0] = pb[0];
                bf[nt][1] = pb[4 * SB];
            }
            #pragma unroll
            for (int mt = 0; mt < 4; mt++)
                #pragma unroll
                for (int nt = 0; nt < 4; nt++)
                    mma_tf32(acc[mt][nt], af[mt], bf[nt]);
        }

        cp_wait<1>();
        __syncthreads();
    }

    #pragma unroll
    for (int mt = 0; mt < 4; mt++) {
        #pragma unroll
        for (int rr = 0; rr < 2; rr++) {
            const int row = cRow * 128 + warpRow * 64 + mt * 16 + gr + rr * 8;
            #pragma unroll
            for (int nt = 0; nt < 4; nt++) {
                const int col = cCol * 128 + warpCol * 32 + nt * 8 + 2 * ctg;
                float v0 = acc[mt][nt][rr * 2 + 0];
                float v1 = acc[mt][nt][rr * 2 + 1];
                if (OP == 1) {
                    float2 bi = *reinterpret_cast<const float2*>(bias + col);
                    float2 rv = *reinterpret_cast<const float2*>(res + (size_t)row * N + col);
                    v0 += bi.x + rv.x;
                    v1 += bi.y + rv.y;
                } else if (OP == 2) {
                    float2 bi = *reinterpret_cast<const float2*>(bias + col);
                    v0 = gelu_exact(v0 + bi.x);
                    v1 = gelu_exact(v1 + bi.y);
                }
                if (ROUND_OUT) { v0 = tf32r(v0); v1 = tf32r(v1); }
                *reinterpret_cast<float2*>(C + (size_t)row * N + col) = make_float2(v0, v1);
            }
        }
    }
}

// ---------------------------------------------------------------------------
// Flash attention: exact R4 structure (BQ=64, 128 threads, 4 warps), but
// qkv arrives tf32-pre-rounded (qkv GEMM ROUND_OUT=1) -> raw float4 loads,
// zero cvt in the load loops.
// ---------------------------------------------------------------------------
#define SATT 68
#define ATT_TILE (64 * SATT)
#define ATTN_SMEM_BYTES (4 * ATT_TILE * 4)

__global__ void __launch_bounds__(128)
attn_tc(const float* __restrict__ qkv, float* __restrict__ out) {
    extern __shared__ float sm[];
    float* Qs = sm;
    float* Ks = sm + ATT_TILE;
    float* Vs = sm + 2 * ATT_TILE;
    float* Ps = sm + 3 * ATT_TILE;
    const uint32_t* uQ = reinterpret_cast<const uint32_t*>(Qs);
    const uint32_t* uK = reinterpret_cast<const uint32_t*>(Ks);
    const uint32_t* uV = reinterpret_cast<const uint32_t*>(Vs);
    const uint32_t* uP = reinterpret_cast<const uint32_t*>(Ps);

    const int t     = threadIdx.x;
    const int warp  = t >> 5;
    const int lane  = t & 31;
    const int gr    = lane >> 2;
    const int ctg   = lane & 3;
    const int mbase = warp * 16;

    const int qb = blockIdx.x;
    const int bh = blockIdx.y;
    const int bb = bh >> 4;
    const int h  = bh & 15;
    const int tok0 = bb * SEQ;

    // ---- load Q tile raw (pre-rounded by qkv GEMM) ----
    #pragma unroll
    for (int i = 0; i < 8; i++) {
        int idx = t + i * 128;
        int row = idx >> 4;
        int c   = (idx & 15) << 2;
        *reinterpret_cast<float4*>(&Qs[row * SATT + c]) =
            *reinterpret_cast<const float4*>(
                qkv + (size_t)(tok0 + qb * 64 + row) * 3072 + h * 64 + c);
    }

    float m0 = -1e30f, m1 = -1e30f, l0 = 0.f, l1 = 0.f;
    float o[8][4];
    #pragma unroll
    for (int nt = 0; nt < 8; nt++)
        #pragma unroll
        for (int k = 0; k < 4; k++) o[nt][k] = 0.f;

    for (int kb = 0; kb < SEQ / 64; kb++) {
        __syncthreads();

        // ---- load K, V tiles raw ----
        #pragma unroll
        for (int i = 0; i < 8; i++) {
            int idx = t + i * 128;
            int row = idx >> 4;
            int c   = (idx & 15) << 2;
            const float* base = qkv + (size_t)(tok0 + kb * 64 + row) * 3072 + h * 64 + c;
            *reinterpret_cast<float4*>(&Ks[row * SATT + c]) =
                *reinterpret_cast<const float4*>(base + 1024);
            *reinterpret_cast<float4*>(&Vs[row * SATT + c]) =
                *reinterpret_cast<const float4*>(base + 2048);
        }
        __syncthreads();

        float s[8][4];
        #pragma unroll
        for (int nt = 0; nt < 8; nt++)
            #pragma unroll
            for (int k = 0; k < 4; k++) s[nt][k] = 0.f;

        #pragma unroll
        for (int ks = 0; ks < 8; ks++) {
            uint32_t af[4];
            const uint32_t* pa = uQ + (mbase + gr) * SATT + ks * 8 + ctg;
            af[0] = pa[0];
            af[1] = pa[8 * SATT];
            af[2] = pa[4];
            af[3] = pa[8 * SATT + 4];
            #pragma unroll
            for (int nt = 0; nt < 8; nt++) {
                uint32_t bf[2];
                const uint32_t* pb = uK + (nt * 8 + gr) * SATT + ks * 8 + ctg;
                bf[0] = pb[0];
                bf[1] = pb[4];
                mma_tf32(s[nt], af, bf);
            }
        }

        float mx0 = -1e30f, mx1 = -1e30f;
        #pragma unroll
        for (int nt = 0; nt < 8; nt++) {
            s[nt][0] *= 0.125f; s[nt][1] *= 0.125f;
            s[nt][2] *= 0.125f; s[nt][3] *= 0.125f;
            mx0 = fmaxf(mx0, fmaxf(s[nt][0], s[nt][1]));
            mx1 = fmaxf(mx1, fmaxf(s[nt][2], s[nt][3]));
        }
        mx0 = fmaxf(mx0, __shfl_xor_sync(0xffffffffu, mx0, 1));
        mx0 = fmaxf(mx0, __shfl_xor_sync(0xffffffffu, mx0, 2));
        mx1 = fmaxf(mx1, __shfl_xor_sync(0xffffffffu, mx1, 1));
        mx1 = fmaxf(mx1, __shfl_xor_sync(0xffffffffu, mx1, 2));

        float mn0 = fmaxf(m0, mx0), mn1 = fmaxf(m1, mx1);
        float corr0 = __expf(m0 - mn0), corr1 = __expf(m1 - mn1);
        float sum0 = 0.f, sum1 = 0.f;
        #pragma unroll
        for (int nt = 0; nt < 8; nt++) {
            s[nt][0] = __expf(s[nt][0] - mn0);
            s[nt][1] = __expf(s[nt][1] - mn0);
            s[nt][2] = __expf(s[nt][2] - mn1);
            s[nt][3] = __expf(s[nt][3] - mn1);
            sum0 += s[nt][0] + s[nt][1];
            sum1 += s[nt][2] + s[nt][3];
        }
        sum0 += __shfl_xor_sync(0xffffffffu, sum0, 1);
        sum0 += __shfl_xor_sync(0xffffffffu, sum0, 2);
        sum1 += __shfl_xor_sync(0xffffffffu, sum1, 1);
        sum1 += __shfl_xor_sync(0xffffffffu, sum1, 2);

        l0 = l0 * corr0 + sum0;  m0 = mn0;
        l1 = l1 * corr1 + sum1;  m1 = mn1;

        #pragma unroll
        for (int nt = 0; nt < 8; nt++) {
            o[nt][0] *= corr0; o[nt][1] *= corr0;
            o[nt][2] *= corr1; o[nt][3] *= corr1;
        }

        #pragma unroll
        for (int nt = 0; nt < 8; nt++) {
            *reinterpret_cast<float2*>(&Ps[(mbase + gr) * SATT + nt * 8 + 2 * ctg]) =
                make_float2(tf32r(s[nt][0]), tf32r(s[nt][1]));
            *reinterpret_cast<float2*>(&Ps[(mbase + gr + 8) * SATT + nt * 8 + 2 * ctg]) =
                make_float2(tf32r(s[nt][2]), tf32r(s[nt][3]));
        }
        __syncwarp();

        #pragma unroll
        for (int ks = 0; ks < 8; ks++) {
            uint32_t af[4];
            const uint32_t* pa = uP + (mbase + gr) * SATT + ks * 8 + ctg;
            af[0] = pa[0];
            af[1] = pa[8 * SATT];
            af[2] = pa[4];
            af[3] = pa[8 * SATT + 4];
            #pragma unroll
            for (int nt = 0; nt < 8; nt++) {
                uint32_t bf[2];
                const uint32_t* pb = uV + (ks * 8 + ctg) * SATT + nt * 8 + gr;
                bf[0] = pb[0];
                bf[1] = pb[4 * SATT];
                mma_tf32(o[nt], af, bf);
            }
        }
    }

    const float inv0 = 1.0f / l0, inv1 = 1.0f / l1;
    const int row0 = tok0 + qb * 64 + mbase + gr;
    #pragma unroll
    for (int nt = 0; nt < 8; nt++) {
        const int col = h * 64 + nt * 8 + 2 * ctg;
        *reinterpret_cast<float2*>(out + (size_t)row0 * WIDTH + col) =
            make_float2(tf32r(o[nt][0] * inv0), tf32r(o[nt][1] * inv0));
        *reinterpret_cast<float2*>(out + (size_t)(row0 + 8) * WIDTH + col) =
            make_float2(tf32r(o[nt][2] * inv1), tf32r(o[nt][3] * inv1));
    }
}

// ---------------------------------------------------------------------------
// Launch
// ---------------------------------------------------------------------------
extern "C" void kernel_launch(void* const* d_in, const int* in_sizes, int n_in,
                              void* d_out, int out_size) {
    const float* x      = (const float*)d_in[0];
    const float* ln1_g  = (const float*)d_in[1];
    const float* ln1_b  = (const float*)d_in[2];
    const float* w_qkv  = (const float*)d_in[3];
    const float* w_proj = (const float*)d_in[4];
    const float* b_proj = (const float*)d_in[5];
    const float* ln2_g  = (const float*)d_in[6];
    const float* ln2_b  = (const float*)d_in[7];
    const float* w_fc1  = (const float*)d_in[8];
    const float* b_fc1  = (const float*)d_in[9];
    const float* w_fc2  = (const float*)d_in[10];
    const float* b_fc2  = (const float*)d_in[11];
    float* out = (float*)d_out;

    void *ph, *pqkv, *pattn, *px1, *pfc1, *pwq, *pwp, *pw1, *pw2;
    cudaGetSymbolAddress(&ph,    g_h);
    cudaGetSymbolAddress(&pqkv,  g_qkv);
    cudaGetSymbolAddress(&pattn, g_attn);
    cudaGetSymbolAddress(&px1,   g_x1);
    cudaGetSymbolAddress(&pfc1,  g_fc1);
    cudaGetSymbolAddress(&pwq,   g_wqkv_r);
    cudaGetSymbolAddress(&pwp,   g_wproj_r);
    cudaGetSymbolAddress(&pw1,   g_wfc1_r);
    cudaGetSymbolAddress(&pw2,   g_wfc2_r);
    float* hbuf  = (float*)ph;
    float* qkvb  = (float*)pqkv;
    float* attnb = (float*)pattn;
    float* x1b   = (float*)px1;
    float* fc1b  = (float*)pfc1;
    float* wqr   = (float*)pwq;
    float* wpr   = (float*)pwp;
    float* w1r   = (float*)pw1;
    float* w2r   = (float*)pw2;

    cudaFuncSetAttribute(gemm_tc<0,1>, cudaFuncAttributeMaxDynamicSharedMemorySize, GEMM_SMEM_BYTES);
    cudaFuncSetAttribute(gemm_tc<1,0>, cudaFuncAttributeMaxDynamicSharedMemorySize, GEMM_SMEM_BYTES);
    cudaFuncSetAttribute(gemm_tc<2,1>, cudaFuncAttributeMaxDynamicSharedMemorySize, GEMM_SMEM_BYTES);
    cudaFuncSetAttribute(attn_tc,      cudaFuncAttributeMaxDynamicSharedMemorySize, ATTN_SMEM_BYTES);

    // 0) round weights to tf32 (4 float4 per thread, n4 divisible by 1024)
    {
        int n;
        n = WIDTH * 3 * WIDTH / 4;  round_tf32_kernel<<<n / 1024, 256>>>(w_qkv, wqr, n);
        n = WIDTH * WIDTH / 4;      round_tf32_kernel<<<n / 1024, 256>>>(w_proj, wpr, n);
        n = WIDTH * HIDDEN / 4;     round_tf32_kernel<<<n / 1024, 256>>>(w_fc1, w1r, n);
        n = HIDDEN * WIDTH / 4;     round_tf32_kernel<<<n / 1024, 256>>>(w_fc2, w2r, n);
    }

    // 1) LN1 (rounded output)
    ln_kernel<<<MTOK, 256>>>(x, ln1_g, ln1_b, hbuf);

    // 2) qkv = h @ w_qkv (ROUNDED output -> attention loads raw bits)
    {
        dim3 grid(3 * WIDTH / 128, MTOK / 128);
        gemm_tc<0,1><<<grid, 256, GEMM_SMEM_BYTES>>>(MTOK, 3 * WIDTH, WIDTH,
                                                     hbuf, wqr, nullptr, nullptr, qkvb);
    }

    // 3) attention (rounded output)
    {
        dim3 grid(SEQ / 64, 2 * HEADS);
        attn_tc<<<grid, 128, ATTN_SMEM_BYTES>>>(qkvb, attnb);
    }

    // 4) x1 = x + attn @ w_proj + b_proj
    {
        dim3 grid(WIDTH / 128, MTOK / 128);
        gemm_tc<1,0><<<grid, 256, GEMM_SMEM_BYTES>>>(MTOK, WIDTH, WIDTH,
                                                     attnb, wpr, b_proj, x, x1b);
    }

    // 5) LN2 (rounded output)
    ln_kernel<<<MTOK, 256>>>(x1b, ln2_g, ln2_b, hbuf);

    // 6) fc1 = gelu(h @ w_fc1 + b_fc1) (rounded output)
    {
        dim3 grid(HIDDEN / 128, MTOK / 128);
        gemm_tc<2,1><<<grid, 256, GEMM_SMEM_BYTES>>>(MTOK, HIDDEN, WIDTH,
                                                     hbuf, w1r, b_fc1, nullptr, fc1b);
    }

    // 7) out = x1 + fc1 @ w_fc2 + b_fc2
    {
        dim3 grid(WIDTH / 128, MTOK / 128);
        gemm_tc<1,0><<<grid, 256, GEMM_SMEM_BYTES>>>(MTOK, WIDTH, HIDDEN,
                                                     fc1b, w2r, b_fc2, x1b, out);
    }
}